// round 15
// baseline (speedup 1.0000x reference)
#include <cuda_runtime.h>
#include <cuda_bf16.h>
#include <cstdint>

#define BB   4
#define SS   2048
#define SKK  2048
#define HH   512
#define NHH  8
#define DSS  64
#define MTOT (BB*SS)            // 8192
#define BATCH_ELEMS (SS*HH)     // 1048576
#define NPART 64
#define EPSN 1e-5f
#define ATTN_SCALE 0.044194173824159216f   // 1/sqrt(512)
#define LOG2E 1.4426950408889634f

#define RS   20   // gemm smem row stride (uints) = 40 bf16 -> ldmatrix conflict-free
#define BSTU 36   // attn smem row stride (uints) = 72 bf16 -> conflict-free
#define ASTG 4    // attention pipeline stages

// ---------------- scratch (static device memory; no allocations) ----------------
__device__ __nv_bfloat16 g_Xq[MTOT*HH];    // normed Q input, bf16
__device__ __nv_bfloat16 g_Xk[MTOT*HH];    // normed K input, bf16
__device__ __nv_bfloat16 g_pQh[MTOT*HH];   // pQ * ATTN_SCALE * log2(e), [m][d]
__device__ __nv_bfloat16 g_pKh[MTOT*HH];   // [m][d]
__device__ __nv_bfloat16 g_pVh[MTOT*HH];   // [m][d]
__device__ float g_O1[MTOT*HH];
__device__ __nv_bfloat16 g_wqh[HH*HH], g_wkh[HH*HH], g_wvh[HH*HH];
__device__ __nv_bfloat16 g_wch[HH*HH], g_wcl[HH*HH];
__device__ float g_part[2][BB][NPART][2];   // Q/K input partial sums
__device__ float g_apart[BB][NHH*16][2];    // O1 partial sums (from attention blocks)

// ---------------- helpers ----------------
__device__ __forceinline__ unsigned packbf(float lo, float hi){
    unsigned r; asm("cvt.rn.bf16x2.f32 %0, %1, %2;" : "=r"(r) : "f"(hi), "f"(lo)); return r;
}
__device__ __forceinline__ unsigned ex2b2(unsigned x){
    unsigned y; asm("ex2.approx.ftz.bf16x2 %0, %1;" : "=r"(y) : "r"(x)); return y;
}
__device__ __forceinline__ void mma_bf16(float c[4], const unsigned a[4], const unsigned b[2]){
    asm volatile("mma.sync.aligned.m16n8k16.row.col.f32.bf16.bf16.f32 "
        "{%0,%1,%2,%3}, {%4,%5,%6,%7}, {%8,%9}, {%0,%1,%2,%3};"
        : "+f"(c[0]), "+f"(c[1]), "+f"(c[2]), "+f"(c[3])
        : "r"(a[0]), "r"(a[1]), "r"(a[2]), "r"(a[3]), "r"(b[0]), "r"(b[1]));
}
__device__ __forceinline__ void ldm_x4(unsigned r[4], uint32_t addr){
    asm volatile("ldmatrix.sync.aligned.m8n8.x4.shared.b16 {%0,%1,%2,%3}, [%4];"
        : "=r"(r[0]), "=r"(r[1]), "=r"(r[2]), "=r"(r[3]) : "r"(addr));
}
__device__ __forceinline__ void ldm_x4_t(unsigned r[4], uint32_t addr){
    asm volatile("ldmatrix.sync.aligned.m8n8.x4.trans.shared.b16 {%0,%1,%2,%3}, [%4];"
        : "=r"(r[0]), "=r"(r[1]), "=r"(r[2]), "=r"(r[3]) : "r"(addr));
}
__device__ __forceinline__ void cp16(uint32_t dst, const void* src){
    asm volatile("cp.async.ca.shared.global [%0], [%1], 16;" :: "r"(dst), "l"(src));
}
__device__ __forceinline__ void cp_commit(){
    asm volatile("cp.async.commit_group;");
}

// ---------------- prep: convert weights to bf16 + input stats, one launch ----------------
__global__ void __launch_bounds__(256) prep_kernel(
    const float* __restrict__ Q, const float* __restrict__ K,
    const float* __restrict__ wq, const float* __restrict__ wk,
    const float* __restrict__ wv, const float* __restrict__ wc)
{
    __shared__ float ss[8], sq[8];
    const int bx = blockIdx.x, t = threadIdx.x;
    if (bx < 256){
        const int i = bx * 256 + t;   // quad index < 65536
        {
            float4 v = ((const float4*)wq)[i];
            ((uint2*)(unsigned*)g_wqh)[i] = make_uint2(packbf(v.x, v.y), packbf(v.z, v.w));
        }
        {
            float4 v = ((const float4*)wk)[i];
            ((uint2*)(unsigned*)g_wkh)[i] = make_uint2(packbf(v.x, v.y), packbf(v.z, v.w));
        }
        {
            float4 v = ((const float4*)wv)[i];
            ((uint2*)(unsigned*)g_wvh)[i] = make_uint2(packbf(v.x, v.y), packbf(v.z, v.w));
        }
        {
            float4 v = ((const float4*)wc)[i];
            unsigned h0 = packbf(v.x, v.y), h1 = packbf(v.z, v.w);
            ((uint2*)(unsigned*)g_wch)[i] = make_uint2(h0, h1);
            float hx = __uint_as_float(h0 << 16), hy = __uint_as_float(h0 & 0xffff0000u);
            float hz = __uint_as_float(h1 << 16), hw = __uint_as_float(h1 & 0xffff0000u);
            ((uint2*)(unsigned*)g_wcl)[i] = make_uint2(packbf(v.x - hx, v.y - hy), packbf(v.z - hz, v.w - hw));
        }
        return;
    }
    const int slot = (bx >= 512) ? 1 : 0;
    const int idx = bx - 256 - slot*256;
    const int batch = idx >> 6, part = idx & 63;
    const float* x = slot ? K : Q;
    const float4* p = (const float4*)(x + (size_t)batch*BATCH_ELEMS + (size_t)part*(BATCH_ELEMS/NPART));
    float s = 0.f, q = 0.f;
#pragma unroll
    for (int i = 0; i < 16; i++){
        float4 v = p[t + 256*i];
        s += v.x + v.y + v.z + v.w;
        q += v.x*v.x + v.y*v.y + v.z*v.z + v.w*v.w;
    }
#pragma unroll
    for (int off = 16; off; off >>= 1){
        s += __shfl_xor_sync(0xffffffffu, s, off);
        q += __shfl_xor_sync(0xffffffffu, q, off);
    }
    const int w = t >> 5;
    if ((t & 31) == 0){ ss[w] = s; sq[w] = q; }
    __syncthreads();
    if (t == 0){
        float S_ = 0.f, Q_ = 0.f;
#pragma unroll
        for (int i = 0; i < 8; i++){ S_ += ss[i]; Q_ += sq[i]; }
        g_part[slot][batch][part][0] = S_;
        g_part[slot][batch][part][1] = Q_;
    }
}

// ---------------- norm Q/K inputs -> bf16 (stats folded in), 4 float4/thread ----------------
__global__ void __launch_bounds__(256) norm_qk(
    const float* __restrict__ Q, const float* __restrict__ K,
    const float* __restrict__ gq, const float* __restrict__ bq,
    const float* __restrict__ gk, const float* __restrict__ bk)
{
    __shared__ float sred[4], smr[2];
    const int tid = threadIdx.x;
    const int slot = (blockIdx.x >= 1024) ? 1 : 0;
    const int base = (blockIdx.x - slot*1024) * 1024 + tid;   // quad index
    const int batch = base >> 18;
    if (tid < 64){
        float s = g_part[slot][batch][tid][0];
        float q = g_part[slot][batch][tid][1];
#pragma unroll
        for (int off = 16; off; off >>= 1){
            s += __shfl_xor_sync(0xffffffffu, s, off);
            q += __shfl_xor_sync(0xffffffffu, q, off);
        }
        if ((tid & 31) == 0){ sred[(tid>>5)*2] = s; sred[(tid>>5)*2+1] = q; }
    }
    __syncthreads();
    if (tid == 0){
        float S = sred[0] + sred[2], Qa = sred[1] + sred[3];
        float mean = S * (1.0f/(float)BATCH_ELEMS);
        float var  = Qa * (1.0f/(float)BATCH_ELEMS) - mean*mean;
        smr[0] = mean; smr[1] = rsqrtf(var + EPSN);
    }
    __syncthreads();
    const float mean = smr[0], rstd = smr[1];

    const float* X = slot ? K : Q;
    const float* gg = slot ? gk : gq;
    const float* bb = slot ? bk : bq;
    unsigned* outHi = slot ? (unsigned*)g_Xk : (unsigned*)g_Xq;
#pragma unroll
    for (int it = 0; it < 4; it++){
        const int i = base + 256*it;
        const int kq = i & 127;
        const float4 x = ((const float4*)X)[i];
        const float4 g4 = ((const float4*)gg)[kq];
        const float4 b4 = ((const float4*)bb)[kq];
        float4 y;
        y.x = (x.x - mean)*rstd*g4.x + b4.x;
        y.y = (x.y - mean)*rstd*g4.y + b4.y;
        y.z = (x.z - mean)*rstd*g4.z + b4.z;
        y.w = (x.w - mean)*rstd*g4.w + b4.w;
        ((uint2*)outHi)[i] = make_uint2(packbf(y.x, y.y), packbf(y.z, y.w));
    }
}

// ---------------- fused Q/K/V projection GEMM, 3-stage cp.async ----------------
__global__ void __launch_bounds__(256, 2) gemm_proj(
    const float* __restrict__ bq, const float* __restrict__ bk, const float* __restrict__ bv)
{
    extern __shared__ unsigned smu[];
    unsigned* As = smu;                      // [3][128][RS]
    unsigned* Ws = smu + 3*128*RS;
    const uint32_t sA = (uint32_t)__cvta_generic_to_shared(As);
    const uint32_t sW = (uint32_t)__cvta_generic_to_shared(Ws);

    const int tid  = threadIdx.x;
    const int lane = tid & 31, w = tid >> 5;
    const int g = lane >> 2, t4 = lane & 3;
    const int which = blockIdx.x >> 2;
    const __nv_bfloat16* A = (which == 0) ? g_Xq : g_Xk;
    const __nv_bfloat16* W = (which == 0) ? g_wqh : (which == 1) ? g_wkh : g_wvh;
    const float* biasp = (which == 0) ? bq : (which == 1) ? bk : bv;
    __nv_bfloat16* outp = (which == 0) ? g_pQh : (which == 1) ? g_pKh : g_pVh;
    const float scl = (which == 0) ? (ATTN_SCALE * LOG2E) : 1.0f;
    const int n0 = (blockIdx.x & 3) * 128;
    const int m0 = blockIdx.y * 128;

    const int mw = w >> 1, nw = w & 1;
    const int mrow = mw * 32, nrow = nw * 64;

    float acc[2][8][4];
#pragma unroll
    for (int i = 0; i < 2; i++)
#pragma unroll
        for (int j = 0; j < 8; j++)
#pragma unroll
            for (int r = 0; r < 4; r++) acc[i][j][r] = 0.f;

    const int aRow  = lane & 15;
    const int aColU = (lane >> 4) << 2;
    const int bRow  = ((lane >> 4) << 3) + (lane & 7);
    const int bColU = ((lane >> 3) & 1) << 2;

    auto loadTile = [&](int kt, int s){
        const int kb = kt * 32;
#pragma unroll
        for (int i = 0; i < 2; i++){
            const int c = tid + 256*i;
            const int row = c >> 2, seg = c & 3;
            cp16(sA + (uint32_t)(s*128*RS + row*RS + seg*4)*4, A + (size_t)(m0 + row)*HH + kb + seg*8);
            cp16(sW + (uint32_t)(s*128*RS + row*RS + seg*4)*4, W + (size_t)(n0 + row)*HH + kb + seg*8);
        }
    };

    loadTile(0, 0); cp_commit();
    loadTile(1, 1); cp_commit();

    for (int kt = 0; kt < 16; kt++){
        const int s = kt % 3;
        if (kt + 2 < 16) loadTile(kt + 2, (kt + 2) % 3);
        cp_commit();
        asm volatile("cp.async.wait_group 2;");
        __syncthreads();

        const uint32_t aBase = sA + (uint32_t)(s*128*RS)*4;
        const uint32_t wBase = sW + (uint32_t)(s*128*RS)*4;
#pragma unroll
        for (int ks = 0; ks < 2; ks++){
            unsigned ah[2][4];
#pragma unroll
            for (int i = 0; i < 2; i++)
                ldm_x4(ah[i], aBase + (uint32_t)((mrow + i*16 + aRow)*RS + ks*8 + aColU)*4);
            unsigned bh[4][4];
#pragma unroll
            for (int jj = 0; jj < 4; jj++)
                ldm_x4(bh[jj], wBase + (uint32_t)((nrow + jj*16 + bRow)*RS + ks*8 + bColU)*4);
#pragma unroll
            for (int i = 0; i < 2; i++)
#pragma unroll
                for (int jj = 0; jj < 4; jj++){
                    mma_bf16(acc[i][2*jj],   ah[i], bh[jj]);
                    mma_bf16(acc[i][2*jj+1], ah[i], bh[jj] + 2);
                }
        }
        __syncthreads();
    }

#pragma unroll
    for (int i = 0; i < 2; i++){
#pragma unroll
        for (int j = 0; j < 8; j++){
            const int col = n0 + nrow + j*8 + 2*t4;
            const float2 bs = *(const float2*)&biasp[col];
#pragma unroll
            for (int hh = 0; hh < 2; hh++){
                const int row = m0 + mrow + i*16 + g + 8*hh;
                float cx = acc[i][j][2*hh]   + bs.x;
                float cy = acc[i][j][2*hh+1] + bs.y;
                ((unsigned*)outp)[(size_t)row*(HH/2) + (col >> 1)] = packbf(cx*scl, cy*scl);
            }
        }
    }
}

// ---------------- final GEMM with FUSED O1 norm: out = O1 + relu(norm(O1).Wc^T + bc) ----------------
// A-path: read O1 fp32, apply set-norm (stats from g_apart), split hi/lo bf16 inline (LDG+STS).
// W-path: wch/wcl via 2-stage cp.async. 3-term bf16 split MMA. 2 blocks/SM -> single wave.
__global__ void __launch_bounds__(256, 2) gemm_final(
    const float* __restrict__ g0, const float* __restrict__ beta0,
    const float* __restrict__ bc, float* __restrict__ out, const float* __restrict__ O1)
{
    extern __shared__ unsigned smu[];
    const int AROWS = 256;
    unsigned* As = smu;                      // [2][256][RS]  (rows 0-127 hi, 128-255 lo)
    unsigned* Ws = smu + 2*AROWS*RS;
    const uint32_t sW = (uint32_t)__cvta_generic_to_shared(Ws);
    const uint32_t sAaddr = (uint32_t)__cvta_generic_to_shared(As);
    __shared__ float sg0[HH], sb0[HH];
    __shared__ float sred[8], smr[2];

    const int tid  = threadIdx.x;
    const int lane = tid & 31, w = tid >> 5;
    const int g = lane >> 2, t4 = lane & 3;
    const int n0 = (int)blockIdx.x * 128;
    const int m0 = blockIdx.y * 128;
    const int batch = m0 >> 11;

    // norm params -> smem; stats from attention partials
    for (int i = tid; i < HH; i += 256){ sg0[i] = g0[i]; sb0[i] = beta0[i]; }
    if (tid < 128){
        float s = g_apart[batch][tid][0];
        float q = g_apart[batch][tid][1];
#pragma unroll
        for (int off = 16; off; off >>= 1){
            s += __shfl_xor_sync(0xffffffffu, s, off);
            q += __shfl_xor_sync(0xffffffffu, q, off);
        }
        if ((tid & 31) == 0){ sred[(tid>>5)*2] = s; sred[(tid>>5)*2+1] = q; }
    }
    __syncthreads();
    if (tid == 0){
        float S = sred[0] + sred[2] + sred[4] + sred[6];
        float Qa = sred[1] + sred[3] + sred[5] + sred[7];
        float mean = S * (1.0f/(float)BATCH_ELEMS);
        float var  = Qa * (1.0f/(float)BATCH_ELEMS) - mean*mean;
        smr[0] = mean; smr[1] = rsqrtf(var + EPSN);
    }
    __syncthreads();
    const float mean = smr[0], rstd = smr[1];

    const int mw = w >> 1, nw = w & 1;
    const int mrow = mw * 32, nrow = nw * 64;

    float acc[2][8][4];
#pragma unroll
    for (int i = 0; i < 2; i++)
#pragma unroll
        for (int j = 0; j < 8; j++)
#pragma unroll
            for (int r = 0; r < 4; r++) acc[i][j][r] = 0.f;

    const int aRow  = lane & 15;
    const int aColU = (lane >> 4) << 2;
    const int bRow  = ((lane >> 4) << 3) + (lane & 7);
    const int bColU = ((lane >> 3) & 1) << 2;

    // W loader (cp.async): 256 rows (wch 0-127 -> smem rows 0-127... wch is 256 n-rows? no:
    // Wh rows 0-127 = wch[n0..n0+127], rows 128-255 = wcl[n0..n0+127]
    auto loadW = [&](int kt, int s){
        const int kb = kt * 32;
#pragma unroll
        for (int i = 0; i < 2; i++){
            const int c = tid + 256*i;
            const int row = c >> 2, seg = c & 3;   // row 0..127
            cp16(sW + (uint32_t)((s*AROWS + row)*RS + seg*4)*4,
                 g_wch + (size_t)(n0 + row)*HH + kb + seg*8);
            cp16(sW + (uint32_t)((s*AROWS + 128 + row)*RS + seg*4)*4,
                 g_wcl + (size_t)(n0 + row)*HH + kb + seg*8);
        }
    };

    // A loader (LDG + inline norm + hi/lo split + STS)
    const int arow = tid >> 1, ahalf = tid & 1;
    auto loadA = [&](int kt, int s){
        const int kb = kt * 32 + ahalf * 16;
        const float* src = O1 + (size_t)(m0 + arow)*HH + kb;
        unsigned* dHi = As + (size_t)(s*AROWS + arow)*RS + ahalf*8;
        unsigned* dLo = dHi + 128*RS;
#pragma unroll
        for (int c4 = 0; c4 < 4; c4++){
            const float4 x = *(const float4*)(src + 4*c4);
            const float4 g4 = *(const float4*)(sg0 + kb + 4*c4);
            const float4 b4 = *(const float4*)(sb0 + kb + 4*c4);
            float y0 = (x.x - mean)*rstd*g4.x + b4.x;
            float y1 = (x.y - mean)*rstd*g4.y + b4.y;
            float y2 = (x.z - mean)*rstd*g4.z + b4.z;
            float y3 = (x.w - mean)*rstd*g4.w + b4.w;
            unsigned h0 = packbf(y0, y1), h1 = packbf(y2, y3);
            *(uint2*)(dHi + c4*2) = make_uint2(h0, h1);
            float l0 = y0 - __uint_as_float(h0 << 16);
            float l1 = y1 - __uint_as_float(h0 & 0xffff0000u);
            float l2 = y2 - __uint_as_float(h1 << 16);
            float l3 = y3 - __uint_as_float(h1 & 0xffff0000u);
            *(uint2*)(dLo + c4*2) = make_uint2(packbf(l0, l1), packbf(l2, l3));
        }
    };

    loadW(0, 0); cp_commit(); loadA(0, 0);
    loadW(1, 1); cp_commit(); loadA(1, 1);

    for (int kt = 0; kt < 16; kt++){
        const int s = kt & 1;
        if (kt + 1 < 16) asm volatile("cp.async.wait_group 1;");
        else             asm volatile("cp.async.wait_group 0;");
        __syncthreads();

        const uint32_t aBase = sAaddr + (uint32_t)(s*AROWS*RS)*4;
        const uint32_t wBase = sW + (uint32_t)(s*AROWS*RS)*4;
#pragma unroll
        for (int ks = 0; ks < 2; ks++){
            unsigned ah[2][4], alo_[2][4];
#pragma unroll
            for (int i = 0; i < 2; i++){
                ldm_x4(ah[i],   aBase + (uint32_t)((mrow + i*16 + aRow)*RS + ks*8 + aColU)*4);
                ldm_x4(alo_[i], aBase + (uint32_t)((128 + mrow + i*16 + aRow)*RS + ks*8 + aColU)*4);
            }
#pragma unroll
            for (int jj = 0; jj < 4; jj++){
                unsigned bh[4], bl[4];
                ldm_x4(bh, wBase + (uint32_t)((nrow + jj*16 + bRow)*RS + ks*8 + bColU)*4);
                ldm_x4(bl, wBase + (uint32_t)((128 + nrow + jj*16 + bRow)*RS + ks*8 + bColU)*4);
#pragma unroll
                for (int i = 0; i < 2; i++){
                    mma_bf16(acc[i][2*jj],   ah[i], bh);
                    mma_bf16(acc[i][2*jj+1], ah[i], bh + 2);
                    mma_bf16(acc[i][2*jj],   ah[i], bl);
                    mma_bf16(acc[i][2*jj+1], ah[i], bl + 2);
                    mma_bf16(acc[i][2*jj],   alo_[i], bh);
                    mma_bf16(acc[i][2*jj+1], alo_[i], bh + 2);
                }
            }
        }
        __syncthreads();   // all warps done with stage s before its refill
        if (kt + 2 < 16){ loadW(kt + 2, s); cp_commit(); loadA(kt + 2, s); }
    }

#pragma unroll
    for (int i = 0; i < 2; i++){
#pragma unroll
        for (int j = 0; j < 8; j++){
            const int col = n0 + nrow + j*8 + 2*t4;
            const float2 bs = *(const float2*)&bc[col];
#pragma unroll
            for (int hh = 0; hh < 2; hh++){
                const int row = m0 + mrow + i*16 + g + 8*hh;
                float cx = acc[i][j][2*hh]   + bs.x;
                float cy = acc[i][j][2*hh+1] + bs.y;
                const float2 rv = *(const float2*)&O1[(size_t)row*HH + col];
                float2 o;
                o.x = rv.x + fmaxf(cx, 0.f);
                o.y = rv.y + fmaxf(cy, 0.f);
                *(float2*)&out[(size_t)row*HH + col] = o;
            }
        }
    }
}

// ---------------- flash attention: bf16x2 ex2 + l via ones-MMA (R14, best) ----------------
__global__ void __launch_bounds__(128, 2) attn_mma(
    const float* __restrict__ Qraw, float* __restrict__ O1)
{
    extern __shared__ unsigned smu[];
    unsigned* KsBase = smu;                  // [ASTG][64][BSTU]
    unsigned* VsBase = smu + ASTG*64*BSTU;   // [ASTG][64][BSTU]
    unsigned* Qs     = smu;                  // staging alias
    __shared__ float sb2[4][2];

    const int tid  = threadIdx.x;
    const int lane = tid & 31, w = tid >> 5;
    const int g = lane >> 2, t4 = lane & 3;

    const int qt = blockIdx.x, h = blockIdx.y, b = blockIdx.z;
    const int hoff = h * DSS;
    const int qrow0 = b * SS + qt * 128;

    const uint32_t smemK = (uint32_t)__cvta_generic_to_shared(KsBase);
    const uint32_t smemV = (uint32_t)__cvta_generic_to_shared(VsBase);
    const uint32_t smemQ = (uint32_t)__cvta_generic_to_shared(Qs);

    {
#pragma unroll
        for (int i = 0; i < 8; i++){
            const int ch = tid + 128*i;
            const int row = ch >> 3, c = ch & 7;
            cp16(smemQ + (uint32_t)(row*BSTU + c*4)*4, g_pQh + (size_t)(qrow0 + row)*HH + hoff + c*8);
        }
        cp_commit();
        asm volatile("cp.async.wait_group 0;");
    }
    __syncthreads();

    unsigned q[2][4][4];
    {
        const int aRow = lane & 15, aColU = (lane >> 4) << 2;
#pragma unroll
        for (int hh = 0; hh < 2; hh++)
#pragma unroll
            for (int kc = 0; kc < 4; kc++)
                ldm_x4(q[hh][kc], smemQ + (uint32_t)((w*32 + hh*16 + aRow)*BSTU + kc*8 + aColU)*4);
    }
    __syncthreads();

    float o[2][8][4];
#pragma unroll
    for (int hh = 0; hh < 2; hh++)
#pragma unroll
        for (int j = 0; j < 8; j++)
#pragma unroll
            for (int r = 0; r < 4; r++) o[hh][j][r] = 0.f;
    float lacc[2][4];
#pragma unroll
    for (int hh = 0; hh < 2; hh++)
#pragma unroll
        for (int r = 0; r < 4; r++) lacc[hh][r] = 0.f;

    const unsigned ones2[2] = {0x3F803F80u, 0x3F803F80u};   // bf16 1.0 x2

    const __nv_bfloat16* gK0 = g_pKh + ((size_t)b * SKK) * HH + hoff;
    const __nv_bfloat16* gV0 = g_pVh + ((size_t)b * SKK) * HH + hoff;

    auto loadKV = [&](int t, int s){
        const __nv_bfloat16* gK = gK0 + (size_t)t*64*HH;
        const __nv_bfloat16* gV = gV0 + (size_t)t*64*HH;
#pragma unroll
        for (int i = 0; i < 4; i++){
            const int ch = tid + 128*i;
            const int row = ch >> 3, c = ch & 7;
            cp16(smemK + (uint32_t)(s*64*BSTU + row*BSTU + c*4)*4, gK + (size_t)row*HH + c*8);
            cp16(smemV + (uint32_t)(s*64*BSTU + row*BSTU + c*4)*4, gV + (size_t)row*HH + c*8);
        }
    };

    loadKV(0, 0); cp_commit();
    loadKV(1, 1); cp_commit();

    const int kRow  = lane & 7;
    const int kColU = (lane >> 3) << 2;
    const int vRow  = lane & 15;
    const int vColU = (lane >> 4) << 2;

    for (int tt = 0; tt < SKK/64; tt += 2){
        asm volatile("cp.async.wait_group 0;");
        __syncthreads();
        if (tt + 2 < SKK/64){ loadKV(tt + 2, (tt + 2) & (ASTG-1)); cp_commit(); }
        if (tt + 3 < SKK/64){ loadKV(tt + 3, (tt + 3) & (ASTG-1)); cp_commit(); }

#pragma unroll
        for (int u = 0; u < 2; u++){
            const int s = (tt + u) & (ASTG-1);
            const uint32_t kBase = smemK + (uint32_t)(s*64*BSTU)*4;
            const uint32_t vBase = smemV + (uint32_t)(s*64*BSTU)*4;

            float sacc[2][8][4];
#pragma unroll
            for (int hh = 0; hh < 2; hh++)
#pragma unroll
                for (int j = 0; j < 8; j++)
#pragma unroll
                    for (int r = 0; r < 4; r++) sacc[hh][j][r] = 0.f;

#pragma unroll
            for (int j = 0; j < 8; j++){
                unsigned kb0[4], kb1[4];
                ldm_x4(kb0, kBase + (uint32_t)((j*8 + kRow)*BSTU + kColU)*4);
                ldm_x4(kb1, kBase + (uint32_t)((j*8 + kRow)*BSTU + 16 + kColU)*4);
#pragma unroll
                for (int hh = 0; hh < 2; hh++){
                    mma_bf16(sacc[hh][j], q[hh][0], kb0);
                    mma_bf16(sacc[hh][j], q[hh][1], kb0 + 2);
                    mma_bf16(sacc[hh][j], q[hh][2], kb1);
                    mma_bf16(sacc[hh][j], q[hh][3], kb1 + 2);
                }
            }

            unsigned pr[2][8][2];
#pragma unroll
            for (int hh = 0; hh < 2; hh++)
#pragma unroll
                for (int j = 0; j < 8; j++){
                    pr[hh][j][0] = ex2b2(packbf(sacc[hh][j][0], sacc[hh][j][1]));
                    pr[hh][j][1] = ex2b2(packbf(sacc[hh][j][2], sacc[hh][j][3]));
                }

#pragma unroll
            for (int kg = 0; kg < 4; kg++){
                unsigned pa[2][4];
#pragma unroll
                for (int hh = 0; hh < 2; hh++){
                    pa[hh][0] = pr[hh][2*kg  ][0];
                    pa[hh][1] = pr[hh][2*kg  ][1];
                    pa[hh][2] = pr[hh][2*kg+1][0];
                    pa[hh][3] = pr[hh][2*kg+1][1];
                    mma_bf16(lacc[hh], pa[hh], ones2);
                }
#pragma unroll
                for (int jp = 0; jp < 4; jp++){
                    unsigned vb[4];
                    ldm_x4_t(vb, vBase + (uint32_t)((kg*16 + vRow)*BSTU + jp*8 + vColU)*4);
#pragma unroll
                    for (int hh = 0; hh < 2; hh++){
                        mma_bf16(o[hh][2*jp],   pa[hh], vb);
                        mma_bf16(o[hh][2*jp+1], pa[hh], vb + 2);
                    }
                }
            }
        }
    }

    float lv[4];
    lv[0] = lacc[0][0]; lv[1] = lacc[0][2];
    lv[2] = lacc[1][0]; lv[3] = lacc[1][2];

    float s1 = 0.f, s2 = 0.f;
#pragma unroll
    for (int hh = 0; hh < 2; hh++){
        const float inv0 = 1.0f / lv[hh*2], inv1 = 1.0f / lv[hh*2+1];
        const int row0 = qrow0 + w*32 + hh*16 + g;
#pragma unroll
        for (int jd = 0; jd < 8; jd++){
            const int col = hoff + jd*8 + 2*t4;
            {
                const float2 qv = *(const float2*)&Qraw[(size_t)row0*HH + col];
                float2 ov; ov.x = qv.x + o[hh][jd][0]*inv0; ov.y = qv.y + o[hh][jd][1]*inv0;
                *(float2*)&O1[(size_t)row0*HH + col] = ov;
                s1 += ov.x + ov.y; s2 += ov.x*ov.x + ov.y*ov.y;
            }
            {
                const float2 qv = *(const float2*)&Qraw[(size_t)(row0+8)*HH + col];
                float2 ov; ov.x = qv.x + o[hh][jd][2]*inv1; ov.y = qv.y + o[hh][jd][3]*inv1;
                *(float2*)&O1[(size_t)(row0+8)*HH + col] = ov;
                s1 += ov.x + ov.y; s2 += ov.x*ov.x + ov.y*ov.y;
            }
        }
    }
#pragma unroll
    for (int off = 16; off; off >>= 1){
        s1 += __shfl_xor_sync(0xffffffffu, s1, off);
        s2 += __shfl_xor_sync(0xffffffffu, s2, off);
    }
    if (lane == 0){ sb2[w][0] = s1; sb2[w][1] = s2; }
    __syncthreads();
    if (tid == 0){
        float a = 0.f, c = 0.f;
#pragma unroll
        for (int i = 0; i < 4; i++){ a += sb2[i][0]; c += sb2[i][1]; }
        g_apart[b][h*16 + qt][0] = a;
        g_apart[b][h*16 + qt][1] = c;
    }
}

// ---------------- launcher ----------------
extern "C" void kernel_launch(void* const* d_in, const int* in_sizes, int n_in,
                              void* d_out, int out_size)
{
    (void)in_sizes; (void)n_in; (void)out_size;
    const float* Q     = (const float*)d_in[0];
    const float* K     = (const float*)d_in[1];
    const float* wq    = (const float*)d_in[2];
    const float* bq    = (const float*)d_in[3];
    const float* wk    = (const float*)d_in[4];
    const float* bk    = (const float*)d_in[5];
    const float* wv    = (const float*)d_in[6];
    const float* bv    = (const float*)d_in[7];
    const float* wc    = (const float*)d_in[8];
    const float* bc    = (const float*)d_in[9];
    const float* gq    = (const float*)d_in[10];
    const float* betaq = (const float*)d_in[11];
    const float* gk    = (const float*)d_in[12];
    const float* betak = (const float*)d_in[13];
    const float* g0    = (const float*)d_in[14];
    const float* beta0 = (const float*)d_in[15];
    float* out = (float*)d_out;

    float* O1p;
    cudaGetSymbolAddress((void**)&O1p, g_O1);

    const int PROJ_SMEM = 3 * 2 * 128 * RS * 4;      // 61440
    const int FIN_SMEM  = 2 * 2 * 256 * RS * 4;      // 81920 (dynamic; +~4.2KB static)
    const int ATTN_SMEM = 2 * ASTG * 64 * BSTU * 4;  // 73728

    cudaFuncSetAttribute(gemm_proj,  cudaFuncAttributeMaxDynamicSharedMemorySize, PROJ_SMEM);
    cudaFuncSetAttribute(gemm_final, cudaFuncAttributeMaxDynamicSharedMemorySize, FIN_SMEM);
    cudaFuncSetAttribute(attn_mma,   cudaFuncAttributeMaxDynamicSharedMemorySize, ATTN_SMEM);

    // 1. weights->bf16 + Q/K input stats
    prep_kernel<<<768, 256>>>(Q, K, wq, wk, wv, wc);
    // 2. normed inputs -> bf16 (stats folded in)
    norm_qk<<<2048, 256>>>(Q, K, gq, betaq, gk, betak);
    // 3. Q/K/V projections, one launch
    gemm_proj<<<dim3(12, 64), 256, PROJ_SMEM>>>(bq, bk, bv);
    // 4. attention + residual + fused O1 stats
    attn_mma<<<dim3(SS/128, NHH, BB), 128, ATTN_SMEM>>>(Q, O1p);
    // 5. out = O1 + relu(norm(O1) @ wc^T + bc)  — O1 norm fused into the GEMM A-path
    gemm_final<<<dim3(4, 64), 256, FIN_SMEM>>>(g0, beta0, bc, out, O1p);
}

// round 16
// speedup vs baseline: 1.0121x; 1.0121x over previous
#include <cuda_runtime.h>
#include <cuda_bf16.h>
#include <cstdint>

#define BB   4
#define SS   2048
#define SKK  2048
#define HH   512
#define NHH  8
#define DSS  64
#define MTOT (BB*SS)            // 8192
#define BATCH_ELEMS (SS*HH)     // 1048576
#define NPART 64
#define EPSN 1e-5f
#define ATTN_SCALE 0.044194173824159216f   // 1/sqrt(512)
#define LOG2E 1.4426950408889634f

#define RS   20   // gemm smem row stride (uints) = 40 bf16 -> ldmatrix conflict-free
#define BSTU 36   // attn smem row stride (uints) = 72 bf16 -> conflict-free
#define ASTG 4    // attention pipeline stages

// ---------------- scratch (static device memory; no allocations) ----------------
__device__ __nv_bfloat16 g_Xq[MTOT*HH];    // normed Q input, bf16
__device__ __nv_bfloat16 g_Xk[MTOT*HH];    // normed K input, bf16
__device__ __nv_bfloat16 g_XoH[MTOT*HH];   // normed O1, bf16 hi
__device__ __nv_bfloat16 g_XoL[MTOT*HH];   // normed O1, bf16 lo
__device__ __nv_bfloat16 g_pQh[MTOT*HH];   // pQ * ATTN_SCALE * log2(e), [m][d]
__device__ __nv_bfloat16 g_pKh[MTOT*HH];   // [m][d]
__device__ __nv_bfloat16 g_pVh[MTOT*HH];   // [m][d]
__device__ float g_O1[MTOT*HH];
__device__ __nv_bfloat16 g_wqh[HH*HH], g_wkh[HH*HH], g_wvh[HH*HH];
__device__ __nv_bfloat16 g_wch[HH*HH], g_wcl[HH*HH];
__device__ float g_part[2][BB][NPART][2];   // Q/K input partial sums
__device__ float g_apart[BB][NHH*16][2];    // O1 partial sums (from attention blocks)

// ---------------- helpers ----------------
__device__ __forceinline__ unsigned packbf(float lo, float hi){
    unsigned r; asm("cvt.rn.bf16x2.f32 %0, %1, %2;" : "=r"(r) : "f"(hi), "f"(lo)); return r;
}
__device__ __forceinline__ unsigned ex2b2(unsigned x){
    unsigned y; asm("ex2.approx.ftz.bf16x2 %0, %1;" : "=r"(y) : "r"(x)); return y;
}
__device__ __forceinline__ void mma_bf16(float c[4], const unsigned a[4], const unsigned b[2]){
    asm volatile("mma.sync.aligned.m16n8k16.row.col.f32.bf16.bf16.f32 "
        "{%0,%1,%2,%3}, {%4,%5,%6,%7}, {%8,%9}, {%0,%1,%2,%3};"
        : "+f"(c[0]), "+f"(c[1]), "+f"(c[2]), "+f"(c[3])
        : "r"(a[0]), "r"(a[1]), "r"(a[2]), "r"(a[3]), "r"(b[0]), "r"(b[1]));
}
__device__ __forceinline__ void ldm_x4(unsigned r[4], uint32_t addr){
    asm volatile("ldmatrix.sync.aligned.m8n8.x4.shared.b16 {%0,%1,%2,%3}, [%4];"
        : "=r"(r[0]), "=r"(r[1]), "=r"(r[2]), "=r"(r[3]) : "r"(addr));
}
__device__ __forceinline__ void ldm_x4_t(unsigned r[4], uint32_t addr){
    asm volatile("ldmatrix.sync.aligned.m8n8.x4.trans.shared.b16 {%0,%1,%2,%3}, [%4];"
        : "=r"(r[0]), "=r"(r[1]), "=r"(r[2]), "=r"(r[3]) : "r"(addr));
}
__device__ __forceinline__ void cp16(uint32_t dst, const void* src){
    asm volatile("cp.async.ca.shared.global [%0], [%1], 16;" :: "r"(dst), "l"(src));
}
__device__ __forceinline__ void cp_commit(){
    asm volatile("cp.async.commit_group;");
}

// ---------------- prep: convert weights to bf16 + input stats, one launch ----------------
__global__ void __launch_bounds__(256) prep_kernel(
    const float* __restrict__ Q, const float* __restrict__ K,
    const float* __restrict__ wq, const float* __restrict__ wk,
    const float* __restrict__ wv, const float* __restrict__ wc)
{
    __shared__ float ss[8], sq[8];
    const int bx = blockIdx.x, t = threadIdx.x;
    if (bx < 256){
        const int i = bx * 256 + t;   // quad index < 65536
        {
            float4 v = ((const float4*)wq)[i];
            ((uint2*)(unsigned*)g_wqh)[i] = make_uint2(packbf(v.x, v.y), packbf(v.z, v.w));
        }
        {
            float4 v = ((const float4*)wk)[i];
            ((uint2*)(unsigned*)g_wkh)[i] = make_uint2(packbf(v.x, v.y), packbf(v.z, v.w));
        }
        {
            float4 v = ((const float4*)wv)[i];
            ((uint2*)(unsigned*)g_wvh)[i] = make_uint2(packbf(v.x, v.y), packbf(v.z, v.w));
        }
        {
            float4 v = ((const float4*)wc)[i];
            unsigned h0 = packbf(v.x, v.y), h1 = packbf(v.z, v.w);
            ((uint2*)(unsigned*)g_wch)[i] = make_uint2(h0, h1);
            float hx = __uint_as_float(h0 << 16), hy = __uint_as_float(h0 & 0xffff0000u);
            float hz = __uint_as_float(h1 << 16), hw = __uint_as_float(h1 & 0xffff0000u);
            ((uint2*)(unsigned*)g_wcl)[i] = make_uint2(packbf(v.x - hx, v.y - hy), packbf(v.z - hz, v.w - hw));
        }
        return;
    }
    const int slot = (bx >= 512) ? 1 : 0;
    const int idx = bx - 256 - slot*256;
    const int batch = idx >> 6, part = idx & 63;
    const float* x = slot ? K : Q;
    const float4* p = (const float4*)(x + (size_t)batch*BATCH_ELEMS + (size_t)part*(BATCH_ELEMS/NPART));
    float s = 0.f, q = 0.f;
#pragma unroll
    for (int i = 0; i < 16; i++){
        float4 v = p[t + 256*i];
        s += v.x + v.y + v.z + v.w;
        q += v.x*v.x + v.y*v.y + v.z*v.z + v.w*v.w;
    }
#pragma unroll
    for (int off = 16; off; off >>= 1){
        s += __shfl_xor_sync(0xffffffffu, s, off);
        q += __shfl_xor_sync(0xffffffffu, q, off);
    }
    const int w = t >> 5;
    if ((t & 31) == 0){ ss[w] = s; sq[w] = q; }
    __syncthreads();
    if (t == 0){
        float S_ = 0.f, Q_ = 0.f;
#pragma unroll
        for (int i = 0; i < 8; i++){ S_ += ss[i]; Q_ += sq[i]; }
        g_part[slot][batch][part][0] = S_;
        g_part[slot][batch][part][1] = Q_;
    }
}

// ---------------- norm Q/K inputs -> bf16 (stats folded in), 4 float4/thread ----------------
__global__ void __launch_bounds__(256) norm_qk(
    const float* __restrict__ Q, const float* __restrict__ K,
    const float* __restrict__ gq, const float* __restrict__ bq,
    const float* __restrict__ gk, const float* __restrict__ bk)
{
    __shared__ float sred[4], smr[2];
    const int tid = threadIdx.x;
    const int slot = (blockIdx.x >= 1024) ? 1 : 0;
    const int base = (blockIdx.x - slot*1024) * 1024 + tid;   // quad index
    const int batch = base >> 18;
    if (tid < 64){
        float s = g_part[slot][batch][tid][0];
        float q = g_part[slot][batch][tid][1];
#pragma unroll
        for (int off = 16; off; off >>= 1){
            s += __shfl_xor_sync(0xffffffffu, s, off);
            q += __shfl_xor_sync(0xffffffffu, q, off);
        }
        if ((tid & 31) == 0){ sred[(tid>>5)*2] = s; sred[(tid>>5)*2+1] = q; }
    }
    __syncthreads();
    if (tid == 0){
        float S = sred[0] + sred[2], Qa = sred[1] + sred[3];
        float mean = S * (1.0f/(float)BATCH_ELEMS);
        float var  = Qa * (1.0f/(float)BATCH_ELEMS) - mean*mean;
        smr[0] = mean; smr[1] = rsqrtf(var + EPSN);
    }
    __syncthreads();
    const float mean = smr[0], rstd = smr[1];

    const float* X = slot ? K : Q;
    const float* gg = slot ? gk : gq;
    const float* bb = slot ? bk : bq;
    unsigned* outHi = slot ? (unsigned*)g_Xk : (unsigned*)g_Xq;
#pragma unroll
    for (int it = 0; it < 4; it++){
        const int i = base + 256*it;
        const int kq = i & 127;
        const float4 x = ((const float4*)X)[i];
        const float4 g4 = ((const float4*)gg)[kq];
        const float4 b4 = ((const float4*)bb)[kq];
        float4 y;
        y.x = (x.x - mean)*rstd*g4.x + b4.x;
        y.y = (x.y - mean)*rstd*g4.y + b4.y;
        y.z = (x.z - mean)*rstd*g4.z + b4.z;
        y.w = (x.w - mean)*rstd*g4.w + b4.w;
        ((uint2*)outHi)[i] = make_uint2(packbf(y.x, y.y), packbf(y.z, y.w));
    }
}

// ---------------- norm O1 -> bf16 hi/lo (stats from attention partials) ----------------
__global__ void __launch_bounds__(256) norm_o1(
    const float* __restrict__ O1,
    const float* __restrict__ g0, const float* __restrict__ beta0)
{
    __shared__ float sred[8], smr[2];
    const int tid = threadIdx.x;
    const int base = blockIdx.x * 1024 + tid;
    const int batch = base >> 18;
    if (tid < 128){
        float s = g_apart[batch][tid][0];
        float q = g_apart[batch][tid][1];
#pragma unroll
        for (int off = 16; off; off >>= 1){
            s += __shfl_xor_sync(0xffffffffu, s, off);
            q += __shfl_xor_sync(0xffffffffu, q, off);
        }
        if ((tid & 31) == 0){ sred[(tid>>5)*2] = s; sred[(tid>>5)*2+1] = q; }
    }
    __syncthreads();
    if (tid == 0){
        float S = sred[0] + sred[2] + sred[4] + sred[6];
        float Qa = sred[1] + sred[3] + sred[5] + sred[7];
        float mean = S * (1.0f/(float)BATCH_ELEMS);
        float var  = Qa * (1.0f/(float)BATCH_ELEMS) - mean*mean;
        smr[0] = mean; smr[1] = rsqrtf(var + EPSN);
    }
    __syncthreads();
    const float mean = smr[0], rstd = smr[1];

#pragma unroll
    for (int it = 0; it < 4; it++){
        const int i = base + 256*it;
        const int kq = i & 127;
        const float4 x = ((const float4*)O1)[i];
        const float4 g4 = ((const float4*)g0)[kq];
        const float4 b4 = ((const float4*)beta0)[kq];
        float4 y;
        y.x = (x.x - mean)*rstd*g4.x + b4.x;
        y.y = (x.y - mean)*rstd*g4.y + b4.y;
        y.z = (x.z - mean)*rstd*g4.z + b4.z;
        y.w = (x.w - mean)*rstd*g4.w + b4.w;
        unsigned h0 = packbf(y.x, y.y), h1 = packbf(y.z, y.w);
        ((uint2*)(unsigned*)g_XoH)[i] = make_uint2(h0, h1);
        float hx = __uint_as_float(h0 << 16), hy = __uint_as_float(h0 & 0xffff0000u);
        float hz = __uint_as_float(h1 << 16), hw = __uint_as_float(h1 & 0xffff0000u);
        ((uint2*)(unsigned*)g_XoL)[i] = make_uint2(packbf(y.x - hx, y.y - hy), packbf(y.z - hz, y.w - hw));
    }
}

// ---------------- fused Q/K/V projection GEMM, 3-stage cp.async ----------------
__global__ void __launch_bounds__(256, 2) gemm_proj(
    const float* __restrict__ bq, const float* __restrict__ bk, const float* __restrict__ bv)
{
    extern __shared__ unsigned smu[];
    unsigned* As = smu;                      // [3][128][RS]
    unsigned* Ws = smu + 3*128*RS;
    const uint32_t sA = (uint32_t)__cvta_generic_to_shared(As);
    const uint32_t sW = (uint32_t)__cvta_generic_to_shared(Ws);

    const int tid  = threadIdx.x;
    const int lane = tid & 31, w = tid >> 5;
    const int g = lane >> 2, t4 = lane & 3;
    const int which = blockIdx.x >> 2;
    const __nv_bfloat16* A = (which == 0) ? g_Xq : g_Xk;
    const __nv_bfloat16* W = (which == 0) ? g_wqh : (which == 1) ? g_wkh : g_wvh;
    const float* biasp = (which == 0) ? bq : (which == 1) ? bk : bv;
    __nv_bfloat16* outp = (which == 0) ? g_pQh : (which == 1) ? g_pKh : g_pVh;
    const float scl = (which == 0) ? (ATTN_SCALE * LOG2E) : 1.0f;
    const int n0 = (blockIdx.x & 3) * 128;
    const int m0 = blockIdx.y * 128;

    const int mw = w >> 1, nw = w & 1;
    const int mrow = mw * 32, nrow = nw * 64;

    float acc[2][8][4];
#pragma unroll
    for (int i = 0; i < 2; i++)
#pragma unroll
        for (int j = 0; j < 8; j++)
#pragma unroll
            for (int r = 0; r < 4; r++) acc[i][j][r] = 0.f;

    const int aRow  = lane & 15;
    const int aColU = (lane >> 4) << 2;
    const int bRow  = ((lane >> 4) << 3) + (lane & 7);
    const int bColU = ((lane >> 3) & 1) << 2;

    auto loadTile = [&](int kt, int s){
        const int kb = kt * 32;
#pragma unroll
        for (int i = 0; i < 2; i++){
            const int c = tid + 256*i;
            const int row = c >> 2, seg = c & 3;
            cp16(sA + (uint32_t)(s*128*RS + row*RS + seg*4)*4, A + (size_t)(m0 + row)*HH + kb + seg*8);
            cp16(sW + (uint32_t)(s*128*RS + row*RS + seg*4)*4, W + (size_t)(n0 + row)*HH + kb + seg*8);
        }
    };

    loadTile(0, 0); cp_commit();
    loadTile(1, 1); cp_commit();

    for (int kt = 0; kt < 16; kt++){
        const int s = kt % 3;
        if (kt + 2 < 16) loadTile(kt + 2, (kt + 2) % 3);
        cp_commit();
        asm volatile("cp.async.wait_group 2;");
        __syncthreads();

        const uint32_t aBase = sA + (uint32_t)(s*128*RS)*4;
        const uint32_t wBase = sW + (uint32_t)(s*128*RS)*4;
#pragma unroll
        for (int ks = 0; ks < 2; ks++){
            unsigned ah[2][4];
#pragma unroll
            for (int i = 0; i < 2; i++)
                ldm_x4(ah[i], aBase + (uint32_t)((mrow + i*16 + aRow)*RS + ks*8 + aColU)*4);
            unsigned bh[4][4];
#pragma unroll
            for (int jj = 0; jj < 4; jj++)
                ldm_x4(bh[jj], wBase + (uint32_t)((nrow + jj*16 + bRow)*RS + ks*8 + bColU)*4);
#pragma unroll
            for (int i = 0; i < 2; i++)
#pragma unroll
                for (int jj = 0; jj < 4; jj++){
                    mma_bf16(acc[i][2*jj],   ah[i], bh[jj]);
                    mma_bf16(acc[i][2*jj+1], ah[i], bh[jj] + 2);
                }
        }
        __syncthreads();
    }

#pragma unroll
    for (int i = 0; i < 2; i++){
#pragma unroll
        for (int j = 0; j < 8; j++){
            const int col = n0 + nrow + j*8 + 2*t4;
            const float2 bs = *(const float2*)&biasp[col];
#pragma unroll
            for (int hh = 0; hh < 2; hh++){
                const int row = m0 + mrow + i*16 + g + 8*hh;
                float cx = acc[i][j][2*hh]   + bs.x;
                float cy = acc[i][j][2*hh+1] + bs.y;
                ((unsigned*)outp)[(size_t)row*(HH/2) + (col >> 1)] = packbf(cx*scl, cy*scl);
            }
        }
    }
}

// ---------------- final GEMM: out = res + relu(A.W^T + bias), 3-term bf16 split ----------------
// 2-stage pipeline, 2 blocks/SM -> 256 blocks fit one wave.
__global__ void __launch_bounds__(256, 2) gemm_final(
    const float* __restrict__ bc, float* __restrict__ out, const float* __restrict__ res)
{
    extern __shared__ unsigned smu[];
    const int AROWS = 256;
    unsigned* As = smu;                      // [2][256][RS]
    unsigned* Ws = smu + 2*AROWS*RS;
    const uint32_t sA = (uint32_t)__cvta_generic_to_shared(As);
    const uint32_t sW = (uint32_t)__cvta_generic_to_shared(Ws);

    const int tid  = threadIdx.x;
    const int lane = tid & 31, w = tid >> 5;
    const int g = lane >> 2, t4 = lane & 3;
    const int n0 = (int)blockIdx.x * 128;
    const int m0 = blockIdx.y * 128;

    const int mw = w >> 1, nw = w & 1;
    const int mrow = mw * 32, nrow = nw * 64;

    float acc[2][8][4];
#pragma unroll
    for (int i = 0; i < 2; i++)
#pragma unroll
        for (int j = 0; j < 8; j++)
#pragma unroll
            for (int r = 0; r < 4; r++) acc[i][j][r] = 0.f;

    const int aRow  = lane & 15;
    const int aColU = (lane >> 4) << 2;
    const int bRow  = ((lane >> 4) << 3) + (lane & 7);
    const int bColU = ((lane >> 3) & 1) << 2;

    auto loadTile = [&](int kt, int s){
        const int kb = kt * 32;
#pragma unroll
        for (int i = 0; i < 4; i++){
            const int c = tid + 256*i;
            const int row = c >> 2, seg = c & 3;
            const __nv_bfloat16* srcA = (row >= 128)
                ? (g_XoL + (size_t)(m0 + row - 128)*HH + kb + seg*8)
                : (g_XoH + (size_t)(m0 + row)*HH + kb + seg*8);
            cp16(sA + (uint32_t)(s*AROWS*RS + row*RS + seg*4)*4, srcA);
            const __nv_bfloat16* srcW = (row >= 128)
                ? (g_wcl + (size_t)(n0 + row - 128)*HH + kb + seg*8)
                : (g_wch + (size_t)(n0 + row)*HH + kb + seg*8);
            cp16(sW + (uint32_t)(s*AROWS*RS + row*RS + seg*4)*4, srcW);
        }
    };

    loadTile(0, 0); cp_commit();
    loadTile(1, 1); cp_commit();

    for (int kt = 0; kt < 16; kt++){
        const int s = kt & 1;
        if (kt + 1 < 16) asm volatile("cp.async.wait_group 1;");
        else             asm volatile("cp.async.wait_group 0;");
        __syncthreads();

        const uint32_t aBase = sA + (uint32_t)(s*AROWS*RS)*4;
        const uint32_t wBase = sW + (uint32_t)(s*AROWS*RS)*4;
#pragma unroll
        for (int ks = 0; ks < 2; ks++){
            unsigned ah[2][4], alo_[2][4];
#pragma unroll
            for (int i = 0; i < 2; i++){
                ldm_x4(ah[i],   aBase + (uint32_t)((mrow + i*16 + aRow)*RS + ks*8 + aColU)*4);
                ldm_x4(alo_[i], aBase + (uint32_t)((128 + mrow + i*16 + aRow)*RS + ks*8 + aColU)*4);
            }
#pragma unroll
            for (int jj = 0; jj < 4; jj++){
                unsigned bh[4], bl[4];
                ldm_x4(bh, wBase + (uint32_t)((nrow + jj*16 + bRow)*RS + ks*8 + bColU)*4);
                ldm_x4(bl, wBase + (uint32_t)((128 + nrow + jj*16 + bRow)*RS + ks*8 + bColU)*4);
#pragma unroll
                for (int i = 0; i < 2; i++){
                    mma_bf16(acc[i][2*jj],   ah[i], bh);
                    mma_bf16(acc[i][2*jj+1], ah[i], bh + 2);
                    mma_bf16(acc[i][2*jj],   ah[i], bl);
                    mma_bf16(acc[i][2*jj+1], ah[i], bl + 2);
                    mma_bf16(acc[i][2*jj],   alo_[i], bh);
                    mma_bf16(acc[i][2*jj+1], alo_[i], bh + 2);
                }
            }
        }
        __syncthreads();
        if (kt + 2 < 16){ loadTile(kt + 2, s); cp_commit(); }
    }

#pragma unroll
    for (int i = 0; i < 2; i++){
#pragma unroll
        for (int j = 0; j < 8; j++){
            const int col = n0 + nrow + j*8 + 2*t4;
            const float2 bs = *(const float2*)&bc[col];
#pragma unroll
            for (int hh = 0; hh < 2; hh++){
                const int row = m0 + mrow + i*16 + g + 8*hh;
                float cx = acc[i][j][2*hh]   + bs.x;
                float cy = acc[i][j][2*hh+1] + bs.y;
                const float2 rv = *(const float2*)&res[(size_t)row*HH + col];
                float2 o;
                o.x = rv.x + fmaxf(cx, 0.f);
                o.y = rv.y + fmaxf(cy, 0.f);
                *(float2*)&out[(size_t)row*HH + col] = o;
            }
        }
    }
}

// ---------------- flash attention: bf16x2 ex2 fused into S-loop + l via ones-MMA ----------------
// sacc[*][j] is final at end of S-iteration j -> ex2+pack hoisted there: sacc live range
// drops 64->8 regs (relieves 255-reg ceiling) and MUFU overlaps j+1's independent S-MMAs.
// PV phase unchanged. 128-thr blocks, 2 blocks/SM; warp owns 32 q-rows x 64 keys.
__global__ void __launch_bounds__(128, 2) attn_mma(
    const float* __restrict__ Qraw, float* __restrict__ O1)
{
    extern __shared__ unsigned smu[];
    unsigned* KsBase = smu;                  // [ASTG][64][BSTU]
    unsigned* VsBase = smu + ASTG*64*BSTU;   // [ASTG][64][BSTU]
    unsigned* Qs     = smu;                  // staging alias
    __shared__ float sb2[4][2];

    const int tid  = threadIdx.x;
    const int lane = tid & 31, w = tid >> 5;
    const int g = lane >> 2, t4 = lane & 3;

    const int qt = blockIdx.x, h = blockIdx.y, b = blockIdx.z;
    const int hoff = h * DSS;
    const int qrow0 = b * SS + qt * 128;

    const uint32_t smemK = (uint32_t)__cvta_generic_to_shared(KsBase);
    const uint32_t smemV = (uint32_t)__cvta_generic_to_shared(VsBase);
    const uint32_t smemQ = (uint32_t)__cvta_generic_to_shared(Qs);

    {
#pragma unroll
        for (int i = 0; i < 8; i++){
            const int ch = tid + 128*i;
            const int row = ch >> 3, c = ch & 7;
            cp16(smemQ + (uint32_t)(row*BSTU + c*4)*4, g_pQh + (size_t)(qrow0 + row)*HH + hoff + c*8);
        }
        cp_commit();
        asm volatile("cp.async.wait_group 0;");
    }
    __syncthreads();

    unsigned q[2][4][4];
    {
        const int aRow = lane & 15, aColU = (lane >> 4) << 2;
#pragma unroll
        for (int hh = 0; hh < 2; hh++)
#pragma unroll
            for (int kc = 0; kc < 4; kc++)
                ldm_x4(q[hh][kc], smemQ + (uint32_t)((w*32 + hh*16 + aRow)*BSTU + kc*8 + aColU)*4);
    }
    __syncthreads();

    float o[2][8][4];
#pragma unroll
    for (int hh = 0; hh < 2; hh++)
#pragma unroll
        for (int j = 0; j < 8; j++)
#pragma unroll
            for (int r = 0; r < 4; r++) o[hh][j][r] = 0.f;
    float lacc[2][4];
#pragma unroll
    for (int hh = 0; hh < 2; hh++)
#pragma unroll
        for (int r = 0; r < 4; r++) lacc[hh][r] = 0.f;

    const unsigned ones2[2] = {0x3F803F80u, 0x3F803F80u};   // bf16 1.0 x2

    const __nv_bfloat16* gK0 = g_pKh + ((size_t)b * SKK) * HH + hoff;
    const __nv_bfloat16* gV0 = g_pVh + ((size_t)b * SKK) * HH + hoff;

    auto loadKV = [&](int t, int s){
        const __nv_bfloat16* gK = gK0 + (size_t)t*64*HH;
        const __nv_bfloat16* gV = gV0 + (size_t)t*64*HH;
#pragma unroll
        for (int i = 0; i < 4; i++){
            const int ch = tid + 128*i;
            const int row = ch >> 3, c = ch & 7;
            cp16(smemK + (uint32_t)(s*64*BSTU + row*BSTU + c*4)*4, gK + (size_t)row*HH + c*8);
            cp16(smemV + (uint32_t)(s*64*BSTU + row*BSTU + c*4)*4, gV + (size_t)row*HH + c*8);
        }
    };

    loadKV(0, 0); cp_commit();
    loadKV(1, 1); cp_commit();

    const int kRow  = lane & 7;
    const int kColU = (lane >> 3) << 2;
    const int vRow  = lane & 15;
    const int vColU = (lane >> 4) << 2;

    for (int tt = 0; tt < SKK/64; tt += 2){
        asm volatile("cp.async.wait_group 0;");
        __syncthreads();
        if (tt + 2 < SKK/64){ loadKV(tt + 2, (tt + 2) & (ASTG-1)); cp_commit(); }
        if (tt + 3 < SKK/64){ loadKV(tt + 3, (tt + 3) & (ASTG-1)); cp_commit(); }

#pragma unroll
        for (int u = 0; u < 2; u++){
            const int s = (tt + u) & (ASTG-1);
            const uint32_t kBase = smemK + (uint32_t)(s*64*BSTU)*4;
            const uint32_t vBase = smemV + (uint32_t)(s*64*BSTU)*4;

            // ---- S = Q K^T with ex2+pack fused per j-iteration (sacc live range = 8 regs)
            unsigned pr[2][8][2];
#pragma unroll
            for (int j = 0; j < 8; j++){
                unsigned kb0[4], kb1[4];
                ldm_x4(kb0, kBase + (uint32_t)((j*8 + kRow)*BSTU + kColU)*4);
                ldm_x4(kb1, kBase + (uint32_t)((j*8 + kRow)*BSTU + 16 + kColU)*4);
#pragma unroll
                for (int hh = 0; hh < 2; hh++){
                    float sacc[4] = {0.f, 0.f, 0.f, 0.f};
                    mma_bf16(sacc, q[hh][0], kb0);
                    mma_bf16(sacc, q[hh][1], kb0 + 2);
                    mma_bf16(sacc, q[hh][2], kb1);
                    mma_bf16(sacc, q[hh][3], kb1 + 2);
                    pr[hh][j][0] = ex2b2(packbf(sacc[0], sacc[1]));
                    pr[hh][j][1] = ex2b2(packbf(sacc[2], sacc[3]));
                }
            }

            // ---- O += P V, l += P . 1 (V frags loaded once per kg/jp)
#pragma unroll
            for (int kg = 0; kg < 4; kg++){
                unsigned pa[2][4];
#pragma unroll
                for (int hh = 0; hh < 2; hh++){
                    pa[hh][0] = pr[hh][2*kg  ][0];
                    pa[hh][1] = pr[hh][2*kg  ][1];
                    pa[hh][2] = pr[hh][2*kg+1][0];
                    pa[hh][3] = pr[hh][2*kg+1][1];
                    mma_bf16(lacc[hh], pa[hh], ones2);
                }
#pragma unroll
                for (int jp = 0; jp < 4; jp++){
                    unsigned vb[4];
                    ldm_x4_t(vb, vBase + (uint32_t)((kg*16 + vRow)*BSTU + jp*8 + vColU)*4);
#pragma unroll
                    for (int hh = 0; hh < 2; hh++){
                        mma_bf16(o[hh][2*jp],   pa[hh], vb);
                        mma_bf16(o[hh][2*jp+1], pa[hh], vb + 2);
                    }
                }
            }
        }
    }

    float lv[4];
    lv[0] = lacc[0][0]; lv[1] = lacc[0][2];
    lv[2] = lacc[1][0]; lv[3] = lacc[1][2];

    float s1 = 0.f, s2 = 0.f;
#pragma unroll
    for (int hh = 0; hh < 2; hh++){
        const float inv0 = 1.0f / lv[hh*2], inv1 = 1.0f / lv[hh*2+1];
        const int row0 = qrow0 + w*32 + hh*16 + g;
#pragma unroll
        for (int jd = 0; jd < 8; jd++){
            const int col = hoff + jd*8 + 2*t4;
            {
                const float2 qv = *(const float2*)&Qraw[(size_t)row0*HH + col];
                float2 ov; ov.x = qv.x + o[hh][jd][0]*inv0; ov.y = qv.y + o[hh][jd][1]*inv0;
                *(float2*)&O1[(size_t)row0*HH + col] = ov;
                s1 += ov.x + ov.y; s2 += ov.x*ov.x + ov.y*ov.y;
            }
            {
                const float2 qv = *(const float2*)&Qraw[(size_t)(row0+8)*HH + col];
                float2 ov; ov.x = qv.x + o[hh][jd][2]*inv1; ov.y = qv.y + o[hh][jd][3]*inv1;
                *(float2*)&O1[(size_t)(row0+8)*HH + col] = ov;
                s1 += ov.x + ov.y; s2 += ov.x*ov.x + ov.y*ov.y;
            }
        }
    }
#pragma unroll
    for (int off = 16; off; off >>= 1){
        s1 += __shfl_xor_sync(0xffffffffu, s1, off);
        s2 += __shfl_xor_sync(0xffffffffu, s2, off);
    }
    if (lane == 0){ sb2[w][0] = s1; sb2[w][1] = s2; }
    __syncthreads();
    if (tid == 0){
        float a = 0.f, c = 0.f;
#pragma unroll
        for (int i = 0; i < 4; i++){ a += sb2[i][0]; c += sb2[i][1]; }
        g_apart[b][h*16 + qt][0] = a;
        g_apart[b][h*16 + qt][1] = c;
    }
}

// ---------------- launcher ----------------
extern "C" void kernel_launch(void* const* d_in, const int* in_sizes, int n_in,
                              void* d_out, int out_size)
{
    (void)in_sizes; (void)n_in; (void)out_size;
    const float* Q     = (const float*)d_in[0];
    const float* K     = (const float*)d_in[1];
    const float* wq    = (const float*)d_in[2];
    const float* bq    = (const float*)d_in[3];
    const float* wk    = (const float*)d_in[4];
    const float* bk    = (const float*)d_in[5];
    const float* wv    = (const float*)d_in[6];
    const float* bv    = (const float*)d_in[7];
    const float* wc    = (const float*)d_in[8];
    const float* bc    = (const float*)d_in[9];
    const float* gq    = (const float*)d_in[10];
    const float* betaq = (const float*)d_in[11];
    const float* gk    = (const float*)d_in[12];
    const float* betak = (const float*)d_in[13];
    const float* g0    = (const float*)d_in[14];
    const float* beta0 = (const float*)d_in[15];
    float* out = (float*)d_out;

    float* O1p;
    cudaGetSymbolAddress((void**)&O1p, g_O1);

    const int PROJ_SMEM = 3 * 2 * 128 * RS * 4;      // 61440
    const int FIN_SMEM  = 2 * 2 * 256 * RS * 4;      // 81920
    const int ATTN_SMEM = 2 * ASTG * 64 * BSTU * 4;  // 73728

    cudaFuncSetAttribute(gemm_proj,  cudaFuncAttributeMaxDynamicSharedMemorySize, PROJ_SMEM);
    cudaFuncSetAttribute(gemm_final, cudaFuncAttributeMaxDynamicSharedMemorySize, FIN_SMEM);
    cudaFuncSetAttribute(attn_mma,   cudaFuncAttributeMaxDynamicSharedMemorySize, ATTN_SMEM);

    // 1. weights->bf16 + Q/K input stats
    prep_kernel<<<768, 256>>>(Q, K, wq, wk, wv, wc);
    // 2. normed inputs -> bf16 (stats folded in)
    norm_qk<<<2048, 256>>>(Q, K, gq, betaq, gk, betak);
    // 3. Q/K/V projections, one launch
    gemm_proj<<<dim3(12, 64), 256, PROJ_SMEM>>>(bq, bk, bv);
    // 4. attention + residual + fused O1 stats
    attn_mma<<<dim3(SS/128, NHH, BB), 128, ATTN_SMEM>>>(Q, O1p);
    // 5. norm O1 -> bf16 hi/lo (stats from attention partials)
    norm_o1<<<1024, 256>>>(O1p, g0, beta0);
    // 6. out = O1 + relu(norm(O1) @ wc^T + bc)
    gemm_final<<<dim3(4, 64), 256, FIN_SMEM>>>(bc, out, O1p);
}